// round 12
// baseline (speedup 1.0000x reference)
#include <cuda_runtime.h>

// ---------------------------------------------------------------------------
// Grid-accelerated exact NN (chamfer forward, masked mean), 5-node graph:
//   zero -> count(+occ masks,+occP) -> single-pass lookback scan (both
//   grids) -> scatter -> search(+fused final reduction).
// Both clouds counting-sorted into 64^3 grid over [-4,4]^3 (h=0.125).
// Search: 8 lanes cooperate per pc0 point (uniform traversal, coalesced
// candidate scanning, group-local shuffle reduction).
// ---------------------------------------------------------------------------

#define NPTS 65536
#define GD   64
#define NC   (GD * GD * GD)
#define H    0.125f
#define INVH 8.0f
#define GOFF 4.0f
#define ST   128
#define W    8                       // lanes per point
#define SB   (NPTS * W / ST)         // 4096 search blocks
#define NTILE 256                    // scan tiles per grid (1024 cells each)

typedef unsigned long long u64;

// Everything that must start at zero each run, packed for ONE zero kernel.
struct ZeroBlock {
    int  count [NC];                 // pc1 grid counts
    int  count0[NC];                 // pc0 grid counts
    u64  occ [GD * GD];              // per (z,y) row: occupied x bits (pc1)
    u64  occX[GD * GD];              // per (z,x) col: occupied y bits (pc1)
    u64  occP[GD];                   // per z plane: nonempty-row y bits
    u64  tstat[2][NTILE];            // lookback state: (sum<<2)|flag
    int  done;                       // search completion counter
    int  pad[3];                     // keep size 16B-aligned
};
__device__ ZeroBlock gz;

__device__ int    g_off    [NC + 1];
__device__ int    g_cursor [NC];
__device__ int    g_off0   [NC + 1];
__device__ int    g_cursor0[NC];
__device__ float4 g_pts [NPTS];      // sorted pc1: (x,y,z,||b||^2)
__device__ float4 g_pts0[NPTS];      // sorted pc0: (x,y,z,||a||^2)
__device__ float  g_block[SB * 2];   // per-block (sum, count)

__device__ __forceinline__ int cellc(float v) {
    int c = (int)floorf((v + GOFF) * INVH);
    return min(GD - 1, max(0, c));
}
__device__ __forceinline__ u64 bitrange(int lo, int hi) {
    return (~0ull << lo) & (~0ull >> (63 - hi));
}

// ---------------------------------------------------------------------------
// K1: zero the packed scratch block with wide strided stores.
// ---------------------------------------------------------------------------
#define ZVECS ((int)(sizeof(ZeroBlock) / 16))
__global__ void zero_k() {
    int i = blockIdx.x * blockDim.x + threadIdx.x;
    int4* p = (int4*)&gz;
    if (i < ZVECS) p[i] = make_int4(0, 0, 0, 0);
}

// ---------------------------------------------------------------------------
__global__ void count_k(const float* __restrict__ pc1,
                        const float* __restrict__ pc0) {
    int i = blockIdx.x * blockDim.x + threadIdx.x;
    {
        float x = pc1[3 * i], y = pc1[3 * i + 1], z = pc1[3 * i + 2];
        int cx = cellc(x), cy = cellc(y), cz = cellc(z);
        atomicAdd(&gz.count[(cz * GD + cy) * GD + cx], 1);
        atomicOr(&gz.occ [cz * GD + cy], 1ull << cx);
        atomicOr(&gz.occX[cz * GD + cx], 1ull << cy);
        atomicOr(&gz.occP[cz], 1ull << cy);
    }
    {
        float x = pc0[3 * i], y = pc0[3 * i + 1], z = pc0[3 * i + 2];
        atomicAdd(&gz.count0[(cellc(z) * GD + cellc(y)) * GD + cellc(x)], 1);
    }
}

// ---------------------------------------------------------------------------
// Single-pass exclusive scan with decoupled lookback. grid = (NTILE, 2).
// Tile = 1024 cells (256 threads x 4). flag: 1=aggregate ready, 2=inclusive.
// All 512 tiles are co-resident (tiny footprint), so lookback cannot starve.
// ---------------------------------------------------------------------------
__global__ void scan_k() {
    int which = blockIdx.y;
    int tile  = blockIdx.x;
    int* cnt = which ? gz.count0  : gz.count;
    int* off = which ? g_off0     : g_off;
    int* cur = which ? g_cursor0  : g_cursor;
    int t = threadIdx.x;
    int base = (tile * 256 + t) * 4;
    int c0 = cnt[base], c1 = cnt[base + 1];
    int c2 = cnt[base + 2], c3 = cnt[base + 3];
    int s = c0 + c1 + c2 + c3;

    __shared__ int sh[256];
    __shared__ int s_prefix;
    sh[t] = s; __syncthreads();
    for (int o = 1; o < 256; o <<= 1) {
        int u = (t >= o) ? sh[t - o] : 0; __syncthreads();
        sh[t] += u; __syncthreads();
    }
    int total = sh[255];

    if (t == 0) {
        u64* st = gz.tstat[which];
        if (tile == 0) {
            s_prefix = 0;
            atomicExch(&st[0], ((u64)total << 2) | 2ull);
        } else {
            atomicExch(&st[tile], ((u64)total << 2) | 1ull);
            long long run = 0;
            int p = tile - 1;
            for (;;) {
                u64 v = atomicAdd(&st[p], 0ull);
                int f = (int)(v & 3ull);
                if (f == 0) continue;                 // predecessor not ready
                run += (long long)(v >> 2);
                if (f == 2) break;                    // inclusive found
                p--;
            }
            s_prefix = (int)run;
            atomicExch(&st[tile], ((u64)(total + run) << 2) | 2ull);
        }
    }
    __syncthreads();
    int prefix = s_prefix;

    int o0 = sh[t] - s + prefix;
    int o1 = o0 + c0, o2 = o1 + c1, o3 = o2 + c2;
    off[base] = o0;     off[base + 1] = o1;
    off[base + 2] = o2; off[base + 3] = o3;
    cur[base] = o0;     cur[base + 1] = o1;
    cur[base + 2] = o2; cur[base + 3] = o3;
    if (tile == NTILE - 1 && t == 0) off[NC] = NPTS;
}

// ---------------------------------------------------------------------------
__global__ void scatter_k(const float* __restrict__ pc1,
                          const float* __restrict__ pc0) {
    int i = blockIdx.x * blockDim.x + threadIdx.x;
    {
        float x = pc1[3 * i], y = pc1[3 * i + 1], z = pc1[3 * i + 2];
        int c = (cellc(z) * GD + cellc(y)) * GD + cellc(x);
        int idx = atomicAdd(&g_cursor[c], 1);
        g_pts[idx] = make_float4(x, y, z, x * x + y * y + z * z);
    }
    {
        float x = pc0[3 * i], y = pc0[3 * i + 1], z = pc0[3 * i + 2];
        int c = (cellc(z) * GD + cellc(y)) * GD + cellc(x);
        int idx = atomicAdd(&g_cursor0[c], 1);
        g_pts0[idx] = make_float4(x, y, z, fmaf(x, x, fmaf(y, y, z * z)));
    }
}

// ---------------------------------------------------------------------------
// Search: 8 lanes per sorted pc0 point. Uniform traversal within the group
// (mask/offset loads broadcast); candidates in a run split lane-cyclically
// (coalesced). Per-shell group min via group-local shfl_xor (group lanes
// always converged: uniform bounds, shared break). Last finishing block
// performs the deterministic final reduction (fixed-order sum).
// ---------------------------------------------------------------------------
__global__ void __launch_bounds__(ST) search_k(float* __restrict__ out) {
    int t = threadIdx.x;
    int gid = blockIdx.x * ST + t;
    int i = gid / W;                         // point index
    int l = gid & (W - 1);                   // lane within group
    unsigned gm = 0xFFu << ((t & 31) & ~(W - 1));  // group-local shuffle mask

    float4 a = __ldg(&g_pts0[i]);
    float nax = -2.f * a.x, nay = -2.f * a.y, naz = -2.f * a.z;
    float asq = a.w;
    int cx = cellc(a.x), cy = cellc(a.y), cz = cellc(a.z);

    float c0a = 1e30f, c1a = 1e30f;

    auto scan_run = [&](int cc0, int cc1) {
        int s = __ldg(&g_off[cc0]);          // uniform in group -> broadcast
        int e = __ldg(&g_off[cc1 + 1]);
        int k = s + l;
        for (; k + W < e; k += 2 * W) {
            float4 p0 = __ldg(&g_pts[k]);
            float4 p1 = __ldg(&g_pts[k + W]);
            c0a = fminf(c0a, fmaf(nax, p0.x, fmaf(nay, p0.y, fmaf(naz, p0.z, p0.w))));
            c1a = fminf(c1a, fmaf(nax, p1.x, fmaf(nay, p1.y, fmaf(naz, p1.z, p1.w))));
        }
        if (k < e) {
            float4 p = __ldg(&g_pts[k]);
            c0a = fminf(c0a, fmaf(nax, p.x, fmaf(nay, p.y, fmaf(naz, p.z, p.w))));
        }
    };

    float m = 1e30f;
    for (int r = 0; r <= 12; r++) {
        int z0 = max(cz - r, 0), z1 = min(cz + r, GD - 1);
        int y0 = max(cy - r, 0), y1 = min(cy + r, GD - 1);
        int xl = cx - r, xr = cx + r;
        int x0 = max(xl, 0), x1 = min(xr, GD - 1);
        u64 xm = bitrange(x0, x1);

        for (int z = z0; z <= z1; z++) {
            int zb = z * GD;
            bool zedge = (z == cz - r) || (z == cz + r);
            if (zedge) {
                u64 wp = __ldg(&gz.occP[z]) & bitrange(y0, y1);
                while (wp) {
                    int y = __ffsll((long long)wp) - 1; wp &= wp - 1;
                    u64 w = __ldg(&gz.occ[zb + y]) & xm;
                    if (w) {
                        int lo = __ffsll((long long)w) - 1;
                        int hi = 63 - __clzll(w);
                        scan_run((zb + y) * GD + lo, (zb + y) * GD + hi);
                    }
                }
            } else {
                int yl = cy - r, yr2 = cy + r;
                if (yl >= 0) {
                    u64 w = __ldg(&gz.occ[zb + yl]) & xm;
                    if (w) {
                        int lo = __ffsll((long long)w) - 1;
                        int hi = 63 - __clzll(w);
                        scan_run((zb + yl) * GD + lo, (zb + yl) * GD + hi);
                    }
                }
                if (yr2 <= GD - 1) {
                    u64 w = __ldg(&gz.occ[zb + yr2]) & xm;
                    if (w) {
                        int lo = __ffsll((long long)w) - 1;
                        int hi = 63 - __clzll(w);
                        scan_run((zb + yr2) * GD + lo, (zb + yr2) * GD + hi);
                    }
                }
                int yi0 = max(yl + 1, 0), yi1 = min(yr2 - 1, GD - 1);
                if (yi0 <= yi1) {
                    u64 ym = bitrange(yi0, yi1);
                    if (xl >= 0) {
                        u64 wc = __ldg(&gz.occX[zb + xl]) & ym;
                        while (wc) {
                            int y = __ffsll((long long)wc) - 1; wc &= wc - 1;
                            int c = (zb + y) * GD + xl;
                            scan_run(c, c);
                        }
                    }
                    if (xr <= GD - 1) {
                        u64 wc = __ldg(&gz.occX[zb + xr]) & ym;
                        while (wc) {
                            int y = __ffsll((long long)wc) - 1; wc &= wc - 1;
                            int c = (zb + y) * GD + xr;
                            scan_run(c, c);
                        }
                    }
                }
            }
        }
        // group min (lanes of a group always converged here)
        float ml = fminf(c0a, c1a);
        ml = fminf(ml, __shfl_xor_sync(gm, ml, 1));
        ml = fminf(ml, __shfl_xor_sync(gm, ml, 2));
        ml = fminf(ml, __shfl_xor_sync(gm, ml, 4));
        m = ml;
        float rh = r * H;
        float rh2 = rh * rh;
        if (m + asq <= rh2 || rh2 > 2.0f) break;   // unscanned have d >= rh2
    }

    float d = m + asq;
    float s = 0.f, c = 0.f;
    if (l == 0 && d <= 2.0f) { s = d; c = 1.f; }   // one lane per point counts

    __shared__ float ss[ST], sc[ST];
    ss[t] = s; sc[t] = c;
    __syncthreads();
    for (int o = ST / 2; o > 0; o >>= 1) {
        if (t < o) { ss[t] += ss[t + o]; sc[t] += sc[t + o]; }
        __syncthreads();
    }
    __shared__ int isLast;
    if (t == 0) {
        g_block[2 * blockIdx.x + 0] = ss[0];
        g_block[2 * blockIdx.x + 1] = sc[0];
        __threadfence();
        isLast = (atomicAdd(&gz.done, 1) == SB - 1);
    }
    __syncthreads();
    if (isLast) {
        // deterministic fixed-order final reduction by the last block
        float fs = 0.f, fc = 0.f;
        for (int k = t; k < SB; k += ST) {
            fs += g_block[2 * k + 0];
            fc += g_block[2 * k + 1];
        }
        ss[t] = fs; sc[t] = fc;
        __syncthreads();
        for (int o = ST / 2; o > 0; o >>= 1) {
            if (t < o) { ss[t] += ss[t + o]; sc[t] += sc[t + o]; }
            __syncthreads();
        }
        if (t == 0) out[0] = ss[0] / sc[0];
    }
}

extern "C" void kernel_launch(void* const* d_in, const int* in_sizes, int n_in,
                              void* d_out, int out_size) {
    const float* pc0 = (const float*)d_in[0];
    const float* pc1 = (const float*)d_in[1];
    (void)in_sizes; (void)n_in; (void)out_size;

    zero_k   <<<(ZVECS + 255) / 256, 256>>>();
    count_k  <<<NPTS / 256, 256>>>(pc1, pc0);
    scan_k   <<<dim3(NTILE, 2), 256>>>();
    scatter_k<<<NPTS / 256, 256>>>(pc1, pc0);
    search_k <<<SB, ST>>>((float*)d_out);
}

// round 13
// speedup vs baseline: 1.0458x; 1.0458x over previous
#include <cuda_runtime.h>

// ---------------------------------------------------------------------------
// Grid-accelerated exact NN (chamfer forward, masked mean), 5-node graph:
//   zero -> count(+occ masks,+occP) -> single-pass lookback scan (both
//   grids, WARP-PARALLEL windowed lookback) -> scatter -> search(+fused
//   final reduction).
// Both clouds counting-sorted into 64^3 grid over [-4,4]^3 (h=0.125).
// ---------------------------------------------------------------------------

#define NPTS 65536
#define GD   64
#define NC   (GD * GD * GD)
#define H    0.125f
#define INVH 8.0f
#define GOFF 4.0f
#define ST   128
#define W    8                       // lanes per point
#define SB   (NPTS * W / ST)         // 4096 search blocks
#define NTILE 256                    // scan tiles per grid (1024 cells each)

typedef unsigned long long u64;
typedef long long s64;

// Everything that must start at zero each run, packed for ONE zero kernel.
struct ZeroBlock {
    int  count [NC];                 // pc1 grid counts
    int  count0[NC];                 // pc0 grid counts
    u64  occ [GD * GD];              // per (z,y) row: occupied x bits (pc1)
    u64  occX[GD * GD];              // per (z,x) col: occupied y bits (pc1)
    u64  occP[GD];                   // per z plane: nonempty-row y bits
    u64  tstat[2][NTILE];            // lookback state: (sum<<2)|flag
    int  done;                       // search completion counter
    int  pad[3];                     // keep size 16B-aligned
};
__device__ ZeroBlock gz;

__device__ int    g_off    [NC + 1];
__device__ int    g_cursor [NC];
__device__ int    g_off0   [NC + 1];
__device__ int    g_cursor0[NC];
__device__ float4 g_pts [NPTS];      // sorted pc1: (x,y,z,||b||^2)
__device__ float4 g_pts0[NPTS];      // sorted pc0: (x,y,z,||a||^2)
__device__ float  g_block[SB * 2];   // per-block (sum, count)

__device__ __forceinline__ int cellc(float v) {
    int c = (int)floorf((v + GOFF) * INVH);
    return min(GD - 1, max(0, c));
}
__device__ __forceinline__ u64 bitrange(int lo, int hi) {
    return (~0ull << lo) & (~0ull >> (63 - hi));
}

// ---------------------------------------------------------------------------
// K1: zero the packed scratch block with wide strided stores.
// ---------------------------------------------------------------------------
#define ZVECS ((int)(sizeof(ZeroBlock) / 16))
__global__ void zero_k() {
    int i = blockIdx.x * blockDim.x + threadIdx.x;
    int4* p = (int4*)&gz;
    if (i < ZVECS) p[i] = make_int4(0, 0, 0, 0);
}

// ---------------------------------------------------------------------------
__global__ void count_k(const float* __restrict__ pc1,
                        const float* __restrict__ pc0) {
    int i = blockIdx.x * blockDim.x + threadIdx.x;
    {
        float x = pc1[3 * i], y = pc1[3 * i + 1], z = pc1[3 * i + 2];
        int cx = cellc(x), cy = cellc(y), cz = cellc(z);
        atomicAdd(&gz.count[(cz * GD + cy) * GD + cx], 1);
        atomicOr(&gz.occ [cz * GD + cy], 1ull << cx);
        atomicOr(&gz.occX[cz * GD + cx], 1ull << cy);
        atomicOr(&gz.occP[cz], 1ull << cy);
    }
    {
        float x = pc0[3 * i], y = pc0[3 * i + 1], z = pc0[3 * i + 2];
        atomicAdd(&gz.count0[(cellc(z) * GD + cellc(y)) * GD + cellc(x)], 1);
    }
}

// ---------------------------------------------------------------------------
// Single-pass exclusive scan, decoupled lookback with a 32-wide parallel
// window (CUB-style). grid = (NTILE, 2); tile = 1024 cells (256 thr x 4).
// flag: 1 = aggregate ready, 2 = inclusive ready. All 512 tiles co-resident.
// ---------------------------------------------------------------------------
__global__ void scan_k() {
    int which = blockIdx.y;
    int tile  = blockIdx.x;
    int* cnt = which ? gz.count0  : gz.count;
    int* off = which ? g_off0     : g_off;
    int* cur = which ? g_cursor0  : g_cursor;
    int t = threadIdx.x;
    int base = (tile * 256 + t) * 4;
    int c0 = cnt[base], c1 = cnt[base + 1];
    int c2 = cnt[base + 2], c3 = cnt[base + 3];
    int s = c0 + c1 + c2 + c3;

    __shared__ int sh[256];
    __shared__ int s_prefix;
    sh[t] = s; __syncthreads();
    for (int o = 1; o < 256; o <<= 1) {
        int u = (t >= o) ? sh[t - o] : 0; __syncthreads();
        sh[t] += u; __syncthreads();
    }
    int total = sh[255];

    if (t < 32) {
        u64* st = gz.tstat[which];
        if (tile == 0) {
            if (t == 0) { s_prefix = 0; atomicExch(&st[0], ((u64)total << 2) | 2ull); }
        } else {
            if (t == 0) atomicExch(&st[tile], ((u64)total << 2) | 1ull);
            s64 run = 0;
            int wbase = tile - 1;
            for (;;) {
                int p = wbase - t;
                s64 agg; int f;
                if (p < 0) { f = 2; agg = 0; }
                else {
                    u64 v;
                    do { v = atomicAdd(&st[p], 0ull); f = (int)(v & 3ull); } while (f == 0);
                    agg = (s64)(v >> 2);
                }
                unsigned b2 = __ballot_sync(0xFFFFFFFFu, f == 2);
                if (b2) {
                    int first2 = __ffs(b2) - 1;           // nearest inclusive
                    s64 contrib = (t <= first2) ? agg : 0;
                    for (int o = 16; o; o >>= 1)
                        contrib += __shfl_down_sync(0xFFFFFFFFu, contrib, o);
                    run += __shfl_sync(0xFFFFFFFFu, contrib, 0);
                    break;
                } else {
                    s64 contrib = agg;
                    for (int o = 16; o; o >>= 1)
                        contrib += __shfl_down_sync(0xFFFFFFFFu, contrib, o);
                    run += __shfl_sync(0xFFFFFFFFu, contrib, 0);
                    wbase -= 32;
                }
            }
            if (t == 0) {
                s_prefix = (int)run;
                atomicExch(&st[tile], ((u64)((s64)total + run) << 2) | 2ull);
            }
        }
    }
    __syncthreads();
    int prefix = s_prefix;

    int o0 = sh[t] - s + prefix;
    int o1 = o0 + c0, o2 = o1 + c1, o3 = o2 + c2;
    off[base] = o0;     off[base + 1] = o1;
    off[base + 2] = o2; off[base + 3] = o3;
    cur[base] = o0;     cur[base + 1] = o1;
    cur[base + 2] = o2; cur[base + 3] = o3;
    if (tile == NTILE - 1 && t == 0) off[NC] = NPTS;
}

// ---------------------------------------------------------------------------
__global__ void scatter_k(const float* __restrict__ pc1,
                          const float* __restrict__ pc0) {
    int i = blockIdx.x * blockDim.x + threadIdx.x;
    {
        float x = pc1[3 * i], y = pc1[3 * i + 1], z = pc1[3 * i + 2];
        int c = (cellc(z) * GD + cellc(y)) * GD + cellc(x);
        int idx = atomicAdd(&g_cursor[c], 1);
        g_pts[idx] = make_float4(x, y, z, x * x + y * y + z * z);
    }
    {
        float x = pc0[3 * i], y = pc0[3 * i + 1], z = pc0[3 * i + 2];
        int c = (cellc(z) * GD + cellc(y)) * GD + cellc(x);
        int idx = atomicAdd(&g_cursor0[c], 1);
        g_pts0[idx] = make_float4(x, y, z, fmaf(x, x, fmaf(y, y, z * z)));
    }
}

// ---------------------------------------------------------------------------
// Search: 8 lanes per sorted pc0 point (uniform traversal, coalesced
// candidate scanning, group-local shuffle reduction). Last finishing block
// performs the deterministic fixed-order final reduction.
// ---------------------------------------------------------------------------
__global__ void __launch_bounds__(ST) search_k(float* __restrict__ out) {
    int t = threadIdx.x;
    int gid = blockIdx.x * ST + t;
    int i = gid / W;                         // point index
    int l = gid & (W - 1);                   // lane within group
    unsigned gm = 0xFFu << ((t & 31) & ~(W - 1));  // group-local shuffle mask

    float4 a = __ldg(&g_pts0[i]);
    float nax = -2.f * a.x, nay = -2.f * a.y, naz = -2.f * a.z;
    float asq = a.w;
    int cx = cellc(a.x), cy = cellc(a.y), cz = cellc(a.z);

    float c0a = 1e30f, c1a = 1e30f;

    auto scan_run = [&](int cc0, int cc1) {
        int s = __ldg(&g_off[cc0]);          // uniform in group -> broadcast
        int e = __ldg(&g_off[cc1 + 1]);
        int k = s + l;
        for (; k + W < e; k += 2 * W) {
            float4 p0 = __ldg(&g_pts[k]);
            float4 p1 = __ldg(&g_pts[k + W]);
            c0a = fminf(c0a, fmaf(nax, p0.x, fmaf(nay, p0.y, fmaf(naz, p0.z, p0.w))));
            c1a = fminf(c1a, fmaf(nax, p1.x, fmaf(nay, p1.y, fmaf(naz, p1.z, p1.w))));
        }
        if (k < e) {
            float4 p = __ldg(&g_pts[k]);
            c0a = fminf(c0a, fmaf(nax, p.x, fmaf(nay, p.y, fmaf(naz, p.z, p.w))));
        }
    };

    float m = 1e30f;
    for (int r = 0; r <= 12; r++) {
        int z0 = max(cz - r, 0), z1 = min(cz + r, GD - 1);
        int y0 = max(cy - r, 0), y1 = min(cy + r, GD - 1);
        int xl = cx - r, xr = cx + r;
        int x0 = max(xl, 0), x1 = min(xr, GD - 1);
        u64 xm = bitrange(x0, x1);

        for (int z = z0; z <= z1; z++) {
            int zb = z * GD;
            bool zedge = (z == cz - r) || (z == cz + r);
            if (zedge) {
                u64 wp = __ldg(&gz.occP[z]) & bitrange(y0, y1);
                while (wp) {
                    int y = __ffsll((long long)wp) - 1; wp &= wp - 1;
                    u64 w = __ldg(&gz.occ[zb + y]) & xm;
                    if (w) {
                        int lo = __ffsll((long long)w) - 1;
                        int hi = 63 - __clzll(w);
                        scan_run((zb + y) * GD + lo, (zb + y) * GD + hi);
                    }
                }
            } else {
                int yl = cy - r, yr2 = cy + r;
                if (yl >= 0) {
                    u64 w = __ldg(&gz.occ[zb + yl]) & xm;
                    if (w) {
                        int lo = __ffsll((long long)w) - 1;
                        int hi = 63 - __clzll(w);
                        scan_run((zb + yl) * GD + lo, (zb + yl) * GD + hi);
                    }
                }
                if (yr2 <= GD - 1) {
                    u64 w = __ldg(&gz.occ[zb + yr2]) & xm;
                    if (w) {
                        int lo = __ffsll((long long)w) - 1;
                        int hi = 63 - __clzll(w);
                        scan_run((zb + yr2) * GD + lo, (zb + yr2) * GD + hi);
                    }
                }
                int yi0 = max(yl + 1, 0), yi1 = min(yr2 - 1, GD - 1);
                if (yi0 <= yi1) {
                    u64 ym = bitrange(yi0, yi1);
                    if (xl >= 0) {
                        u64 wc = __ldg(&gz.occX[zb + xl]) & ym;
                        while (wc) {
                            int y = __ffsll((long long)wc) - 1; wc &= wc - 1;
                            int c = (zb + y) * GD + xl;
                            scan_run(c, c);
                        }
                    }
                    if (xr <= GD - 1) {
                        u64 wc = __ldg(&gz.occX[zb + xr]) & ym;
                        while (wc) {
                            int y = __ffsll((long long)wc) - 1; wc &= wc - 1;
                            int c = (zb + y) * GD + xr;
                            scan_run(c, c);
                        }
                    }
                }
            }
        }
        // group min (lanes of a group always converged here)
        float ml = fminf(c0a, c1a);
        ml = fminf(ml, __shfl_xor_sync(gm, ml, 1));
        ml = fminf(ml, __shfl_xor_sync(gm, ml, 2));
        ml = fminf(ml, __shfl_xor_sync(gm, ml, 4));
        m = ml;
        float rh = r * H;
        float rh2 = rh * rh;
        if (m + asq <= rh2 || rh2 > 2.0f) break;   // unscanned have d >= rh2
    }

    float d = m + asq;
    float s = 0.f, c = 0.f;
    if (l == 0 && d <= 2.0f) { s = d; c = 1.f; }   // one lane per point counts

    __shared__ float ss[ST], sc[ST];
    ss[t] = s; sc[t] = c;
    __syncthreads();
    for (int o = ST / 2; o > 0; o >>= 1) {
        if (t < o) { ss[t] += ss[t + o]; sc[t] += sc[t + o]; }
        __syncthreads();
    }
    __shared__ int isLast;
    if (t == 0) {
        g_block[2 * blockIdx.x + 0] = ss[0];
        g_block[2 * blockIdx.x + 1] = sc[0];
        __threadfence();
        isLast = (atomicAdd(&gz.done, 1) == SB - 1);
    }
    __syncthreads();
    if (isLast) {
        float fs = 0.f, fc = 0.f;
        for (int k = t; k < SB; k += ST) {
            fs += g_block[2 * k + 0];
            fc += g_block[2 * k + 1];
        }
        ss[t] = fs; sc[t] = fc;
        __syncthreads();
        for (int o = ST / 2; o > 0; o >>= 1) {
            if (t < o) { ss[t] += ss[t + o]; sc[t] += sc[t + o]; }
            __syncthreads();
        }
        if (t == 0) out[0] = ss[0] / sc[0];
    }
}

extern "C" void kernel_launch(void* const* d_in, const int* in_sizes, int n_in,
                              void* d_out, int out_size) {
    const float* pc0 = (const float*)d_in[0];
    const float* pc1 = (const float*)d_in[1];
    (void)in_sizes; (void)n_in; (void)out_size;

    zero_k   <<<(ZVECS + 255) / 256, 256>>>();
    count_k  <<<NPTS / 256, 256>>>(pc1, pc0);
    scan_k   <<<dim3(NTILE, 2), 256>>>();
    scatter_k<<<NPTS / 256, 256>>>(pc1, pc0);
    search_k <<<SB, ST>>>((float*)d_out);
}